// round 11
// baseline (speedup 1.0000x reference)
#include <cuda_runtime.h>

// Shapes: field/gt_field (8,4,64,128,64) f32, ct/gt_ct (8,1) f32, sdf (8,1,64,128,64) f32.
// Output: scalar f32 total loss.
// Persistent grid (608 blocks, 7 grid-stride iterations). Each iteration's DRAM
// front (4 centers + 4 gt + sdf = 9 float4/thread) is prefetched into smem with
// cp.async.cg during the PREVIOUS iteration's compute -> continuous DRAM traffic.
// Interior stencil unchanged from R9 (channel-streamed, shfl x-edges).

#define NB 8
#define ND 64
#define NH 128
#define NW 64
#define SP (ND*NH*NW)
#define CS SP
#define NPTS (NB*SP)
#define NVEC (NPTS/4)            // 1048576 float4 quads
#define NBLKP 608                 // 152 SMs * 4 CTAs
#define STRIDE (NBLKP*256)        // 155648
#define NITER 7                   // ceil(NVEC/STRIDE)

#define DXd ((2.0 + 0.5) / 63.0)
#define DYd ((0.5 + 0.5) / 127.0)
#define DZd ((0.3 + 0.5) / 63.0)

constexpr float c_inv2dx = (float)(1.0 / (2.0 * DXd));
constexpr float c_inv2dy = (float)(1.0 / (2.0 * DYd));
constexpr float c_inv2dz = (float)(1.0 / (2.0 * DZd));
constexpr float c_idx2   = (float)(1.0 / (DXd * DXd));
constexpr float c_idy2   = (float)(1.0 / (DYd * DYd));
constexpr float c_idz2   = (float)(1.0 / (DZd * DZd));

constexpr float c_sc_field  = (float)(1.0  / (double)(NB*4*SP));
constexpr float c_sc_ct     = (float)(10.0 / 8.0);
constexpr float c_sc_cm     = (float)(1.0  / (double)(NB*(ND-2)*(NH-2)*(NW-2)));
constexpr float c_sc_noslip = (float)(10.0 / (double)NPTS);
constexpr float c_sc_inlet  = (float)(5.0  / (double)(NB*ND*NH));
constexpr float c_sc_outlet = (float)(1.0  / (double)(NB*ND*NH));

#define INV_RE 1.0e-6f
#define OY NW
#define OZ (NH*NW)
#define FULLMASK 0xffffffffu

__device__ double g_acc = 0.0;
__device__ unsigned int g_count = 0;

__device__ __forceinline__ float4 ld4(const float* p) {
    return *reinterpret_cast<const float4*>(p);
}
__device__ __forceinline__ void cpa16(void* dst_smem, const void* src) {
    unsigned int dsm = (unsigned int)__cvta_generic_to_shared(dst_smem);
    asm volatile("cp.async.cg.shared.global [%0], [%1], 16;\n" :: "r"(dsm), "l"(src) : "memory");
}

// issue the 9-float4 DRAM front for quad `vid` into fbuf[tid][0..8]
__device__ __forceinline__ void prefetch_front(
    float4 (*fbuf)[9], int tid,
    const float* __restrict__ field, const float* __restrict__ gt_field,
    const float* __restrict__ sdf, int vid)
{
    const int wq = vid & 15;
    const int h  = (vid >> 4)  & (NH - 1);
    const int d  = (vid >> 11) & (ND - 1);
    const int b  = vid >> 17;
    const int sidx = ((d * NH + h) << 6) + (wq << 2);
    const float* fb = field    + b * (4 * SP) + sidx;
    const float* gb = gt_field + b * (4 * SP) + sidx;
    #pragma unroll
    for (int c = 0; c < 4; c++) cpa16(&fbuf[tid][c],     fb + c * CS);
    #pragma unroll
    for (int c = 0; c < 4; c++) cpa16(&fbuf[tid][4 + c], gb + c * CS);
    cpa16(&fbuf[tid][8], sdf + b * SP + sidx);
}

__global__ void __launch_bounds__(256, 4) k_loss(
    const float* __restrict__ field,
    const float* __restrict__ ct,
    const float* __restrict__ gt_field,
    const float* __restrict__ gt_ct,
    const float* __restrict__ sdf,
    float* __restrict__ out)
{
    __shared__ float4 fbuf[256][9];    // 36864 B front staging (144 B / thread row)
    __shared__ double warpsum[8];

    const int tid  = threadIdx.x;
    const int vid0 = blockIdx.x * 256 + tid;

    // prologue: prefetch iteration 0's front
    prefetch_front(fbuf, tid, field, gt_field, sdf, (vid0 < NVEC) ? vid0 : 0);
    asm volatile("cp.async.commit_group;\n" ::: "memory");

    float acc = 0.0f;

    #pragma unroll 1
    for (int it = 0; it < NITER; it++) {
        const int vid = vid0 + it * STRIDE;

        // wait for this iteration's front (prefetched last iteration)
        asm volatile("cp.async.wait_group 0;\n" ::: "memory");

        // pull front to registers (conflict-free LDS.128 pattern)
        float4 cv[4], gv[4], svv;
        #pragma unroll
        for (int c = 0; c < 4; c++) cv[c] = fbuf[tid][c];
        #pragma unroll
        for (int c = 0; c < 4; c++) gv[c] = fbuf[tid][4 + c];
        svv = fbuf[tid][8];

        // immediately issue next iteration's front (streams during compute below)
        if (it + 1 < NITER) {
            int vn = vid0 + (it + 1) * STRIDE;
            prefetch_front(fbuf, tid, field, gt_field, sdf, (vn < NVEC) ? vn : 0);
            asm volatile("cp.async.commit_group;\n" ::: "memory");
        }

        if (vid >= NVEC) continue;   // whole-warp granularity (STRIDE, NVEC % 32 == 0)

        const int wq = vid & 15;
        const int h  = (vid >> 4)  & (NH - 1);
        const int d  = (vid >> 11) & (ND - 1);
        const int b  = vid >> 17;
        const int sidx = ((d * NH + h) << 6) + (wq << 2);
        const float* fb = field + b * (4 * SP) + sidx;

        if (vid < 8) {
            float dct = ct[vid] - gt_ct[vid];
            acc += c_sc_ct * dct * dct;
        }

        // velocity centers as scalars
        float Fv[3][4];
        #pragma unroll
        for (int c = 0; c < 3; c++) {
            Fv[c][0] = cv[c].x; Fv[c][1] = cv[c].y;
            Fv[c][2] = cv[c].z; Fv[c][3] = cv[c].w;
        }

        // field MSE, all 4 channels
        {
            float m = 0.0f;
            #pragma unroll
            for (int c = 0; c < 4; c++) {
                float d0 = cv[c].x - gv[c].x, d1 = cv[c].y - gv[c].y;
                float d2 = cv[c].z - gv[c].z, d3 = cv[c].w - gv[c].w;
                m += d0*d0 + d1*d1 + d2*d2 + d3*d3;
            }
            acc += c_sc_field * m;
        }

        float Sv[4] = {svv.x, svv.y, svv.z, svv.w};

        // no-slip (sdf <= 0)
        {
            float m = 0.0f;
            #pragma unroll
            for (int l = 0; l < 4; l++) {
                float q = Fv[0][l]*Fv[0][l] + Fv[1][l]*Fv[1][l] + Fv[2][l]*Fv[2][l];
                m += (Sv[l] <= 0.0f) ? q : 0.0f;
            }
            acc += c_sc_noslip * m;
        }

        // inlet / outlet
        if (wq == 0) {
            float du0 = Fv[0][0] - 1.0f;
            acc += c_sc_inlet * (du0*du0 + Fv[1][0]*Fv[1][0] + Fv[2][0]*Fv[2][0]);
        }
        if (wq == 15) {
            float a0 = Fv[0][3] - Fv[0][2];
            float a1 = Fv[1][3] - Fv[1][2];
            float a2 = Fv[2][3] - Fv[2][2];
            acc += c_sc_outlet * (a0*a0 + a1*a1 + a2*a2);
        }

        const bool yz_interior = (d >= 1) & (d <= ND - 2) & (h >= 1) & (h <= NH - 2);

        // x-edge neighbors via warp shuffle (full warp active here)
        float Lcs[3], Rcs[3];
        #pragma unroll
        for (int c = 0; c < 3; c++) {
            Lcs[c] = __shfl_up_sync  (FULLMASK, Fv[c][3], 1);
            Rcs[c] = __shfl_down_sync(FULLMASK, Fv[c][0], 1);
        }

        // pressure block: gradients; p regs die at end
        float gpx[4], gpy[4], gpz[4];
        {
            float4 pc = cv[3];
            float pL = __shfl_up_sync  (FULLMASK, pc.w, 1);
            float pR = __shfl_down_sync(FULLMASK, pc.x, 1);
            if (yz_interior) {
                const float* cb = fb + 3 * CS;
                float4 yp = ld4(cb + OY), ym = ld4(cb - OY);
                float4 zp = ld4(cb + OZ), zm = ld4(cb - OZ);
                gpy[0] = (yp.x - ym.x) * c_inv2dy;
                gpy[1] = (yp.y - ym.y) * c_inv2dy;
                gpy[2] = (yp.z - ym.z) * c_inv2dy;
                gpy[3] = (yp.w - ym.w) * c_inv2dy;
                gpz[0] = (zp.x - zm.x) * c_inv2dz;
                gpz[1] = (zp.y - zm.y) * c_inv2dz;
                gpz[2] = (zp.z - zm.z) * c_inv2dz;
                gpz[3] = (zp.w - zm.w) * c_inv2dz;
                gpx[0] = (pc.y - pL)   * c_inv2dx;
                gpx[1] = (pc.z - pc.x) * c_inv2dx;
                gpx[2] = (pc.w - pc.y) * c_inv2dx;
                gpx[3] = (pR   - pc.z) * c_inv2dx;
            }
        }

        // interior continuity + momentum, velocity channels streamed
        if (yz_interior) {
            float wgt[4];
            wgt[0] = (wq != 0  && Sv[0] > 0.0f) ? 1.0f : 0.0f;
            wgt[1] = (Sv[1] > 0.0f) ? 1.0f : 0.0f;
            wgt[2] = (Sv[2] > 0.0f) ? 1.0f : 0.0f;
            wgt[3] = (wq != 15 && Sv[3] > 0.0f) ? 1.0f : 0.0f;

            float div[4] = {0.0f, 0.0f, 0.0f, 0.0f};
            float msum = 0.0f;

            #pragma unroll
            for (int c = 0; c < 3; c++) {
                const float* cb = fb + c * CS;
                float4 yp = ld4(cb + OY), ym = ld4(cb - OY);
                float4 zp = ld4(cb + OZ), zm = ld4(cb - OZ);

                float gy[4], sy[4], gz[4], sz[4];
                gy[0] = (yp.x - ym.x) * c_inv2dy; sy[0] = yp.x + ym.x;
                gy[1] = (yp.y - ym.y) * c_inv2dy; sy[1] = yp.y + ym.y;
                gy[2] = (yp.z - ym.z) * c_inv2dy; sy[2] = yp.z + ym.z;
                gy[3] = (yp.w - ym.w) * c_inv2dy; sy[3] = yp.w + ym.w;
                gz[0] = (zp.x - zm.x) * c_inv2dz; sz[0] = zp.x + zm.x;
                gz[1] = (zp.y - zm.y) * c_inv2dz; sz[1] = zp.y + zm.y;
                gz[2] = (zp.z - zm.z) * c_inv2dz; sz[2] = zp.z + zm.z;
                gz[3] = (zp.w - zm.w) * c_inv2dz; sz[3] = zp.w + zm.w;

                #pragma unroll
                for (int l = 0; l < 4; l++) {
                    float ce = Fv[c][l];
                    float xm = (l == 0) ? Lcs[c] : Fv[c][l - 1];
                    float xp = (l == 3) ? Rcs[c] : Fv[c][l + 1];
                    float gx = (xp - xm) * c_inv2dx;
                    float lap = (xp + xm - 2.0f * ce) * c_idx2
                              + (sy[l]   - 2.0f * ce) * c_idy2
                              + (sz[l]   - 2.0f * ce) * c_idz2;
                    float gp  = (c == 0) ? gpx[l] : (c == 1) ? gpy[l] : gpz[l];
                    float res = Fv[0][l] * gx + Fv[1][l] * gy[l] + Fv[2][l] * gz[l]
                              + gp - INV_RE * lap;
                    msum   += wgt[l] * res * res;
                    div[l] += (c == 0) ? gx : (c == 1) ? gy[l] : gz[l];
                }
            }

            #pragma unroll
            for (int l = 0; l < 4; l++)
                msum += wgt[l] * div[l] * div[l];

            acc += c_sc_cm * msum;
        }
    }

    // ---- reduction (once): warp shfl (f32) -> block (f64) -> global atomic ----
    #pragma unroll
    for (int o = 16; o > 0; o >>= 1)
        acc += __shfl_down_sync(FULLMASK, acc, o);

    if ((tid & 31) == 0)
        warpsum[tid >> 5] = (double)acc;
    __syncthreads();

    if (tid == 0) {
        double t = 0.0;
        #pragma unroll
        for (int i = 0; i < 8; i++) t += warpsum[i];
        atomicAdd(&g_acc, t);
        __threadfence();
        unsigned int ticket = atomicAdd(&g_count, 1u);
        if (ticket == (unsigned)(gridDim.x - 1)) {
            double tot = atomicAdd(&g_acc, 0.0);
            out[0] = (float)tot;
            g_acc = 0.0;       // reset for next graph replay
            g_count = 0u;
            __threadfence();
        }
    }
}

extern "C" void kernel_launch(void* const* d_in, const int* in_sizes, int n_in,
                              void* d_out, int out_size)
{
    const float* field    = (const float*)d_in[0];
    const float* ct       = (const float*)d_in[1];
    const float* gt_field = (const float*)d_in[2];
    const float* gt_ct    = (const float*)d_in[3];
    const float* sdf      = (const float*)d_in[4];

    k_loss<<<NBLKP, 256>>>(field, ct, gt_field, gt_ct, sdf, (float*)d_out);
}

// round 12
// speedup vs baseline: 1.2038x; 1.2038x over previous
#include <cuda_runtime.h>

// Shapes: field/gt_field (8,4,64,128,64) f32, ct/gt_ct (8,1) f32, sdf (8,1,64,128,64) f32.
// Output: scalar f32 total loss. R9 structure (float4, shfl x-edges, channel-streamed
// interior, batched front) + gt_field streamed via cp.async.cg into smem, MSE deferred
// to end. field/sdf stay on LDG/L1 path (neighbor reuse lives in L1).

#define NB 8
#define ND 64
#define NH 128
#define NW 64
#define SP (ND*NH*NW)
#define CS SP
#define NPTS (NB*SP)
#define NVEC (NPTS/4)          // 1048576 float4 quads
#define NBLK (NVEC/256)        // 4096 blocks

#define DXd ((2.0 + 0.5) / 63.0)
#define DYd ((0.5 + 0.5) / 127.0)
#define DZd ((0.3 + 0.5) / 63.0)

constexpr float c_inv2dx = (float)(1.0 / (2.0 * DXd));
constexpr float c_inv2dy = (float)(1.0 / (2.0 * DYd));
constexpr float c_inv2dz = (float)(1.0 / (2.0 * DZd));
constexpr float c_idx2   = (float)(1.0 / (DXd * DXd));
constexpr float c_idy2   = (float)(1.0 / (DYd * DYd));
constexpr float c_idz2   = (float)(1.0 / (DZd * DZd));

constexpr float c_sc_field  = (float)(1.0  / (double)(NB*4*SP));
constexpr float c_sc_ct     = (float)(10.0 / 8.0);
constexpr float c_sc_cm     = (float)(1.0  / (double)(NB*(ND-2)*(NH-2)*(NW-2)));
constexpr float c_sc_noslip = (float)(10.0 / (double)NPTS);
constexpr float c_sc_inlet  = (float)(5.0  / (double)(NB*ND*NH));
constexpr float c_sc_outlet = (float)(1.0  / (double)(NB*ND*NH));

#define INV_RE 1.0e-6f
#define OY NW
#define OZ (NH*NW)
#define FULLMASK 0xffffffffu

__device__ double g_acc = 0.0;
__device__ unsigned int g_count = 0;

__device__ __forceinline__ float4 ld4(const float* p) {
    return *reinterpret_cast<const float4*>(p);
}
__device__ __forceinline__ float4 ld4cs(const float* p) {
    return __ldcs(reinterpret_cast<const float4*>(p));
}
__device__ __forceinline__ void cpa16(void* dst_smem, const void* src) {
    unsigned int dsm = (unsigned int)__cvta_generic_to_shared(dst_smem);
    asm volatile("cp.async.cg.shared.global [%0], [%1], 16;\n" :: "r"(dsm), "l"(src) : "memory");
}

__global__ void __launch_bounds__(256, 4) k_loss(
    const float* __restrict__ field,
    const float* __restrict__ ct,
    const float* __restrict__ gt_field,
    const float* __restrict__ gt_ct,
    const float* __restrict__ sdf,
    float* __restrict__ out)
{
    // gt staging: row stride 5 float4s (80 B) -> conflict-free LDS.128 phases
    __shared__ float4 gbuf[256][5];
    __shared__ double warpsum[8];

    const int tid = threadIdx.x;
    const int vid = blockIdx.x * 256 + tid;   // exactly NVEC threads
    const int wq = vid & 15;
    const int h  = (vid >> 4)  & (NH - 1);
    const int d  = (vid >> 11) & (ND - 1);
    const int b  = vid >> 17;

    const int sidx  = ((d * NH + h) << 6) + (wq << 2);
    const float* fb = field    + b * (4 * SP) + sidx;
    const float* gb = gt_field + b * (4 * SP) + sidx;

    // ---- stream gt_field (zero-reuse, 44% of DRAM bytes) via async copy ----
    #pragma unroll
    for (int c = 0; c < 4; c++)
        cpa16(&gbuf[tid][c], gb + c * CS);
    asm volatile("cp.async.commit_group;\n" ::: "memory");

    float acc = 0.0f;

    if (vid < 8) {
        float dct = ct[vid] - gt_ct[vid];
        acc += c_sc_ct * dct * dct;
    }

    // ---- batched DRAM front: 4 centers + sdf (LDG / L1 path) ----
    float4 cv[4], svv;
    #pragma unroll
    for (int c = 0; c < 4; c++) cv[c] = ld4(fb + c * CS);
    svv = ld4cs(sdf + b * SP + sidx);

    // velocity centers persist as scalars
    float Fv[3][4];
    #pragma unroll
    for (int c = 0; c < 3; c++) {
        Fv[c][0] = cv[c].x; Fv[c][1] = cv[c].y;
        Fv[c][2] = cv[c].z; Fv[c][3] = cv[c].w;
    }

    float Sv[4] = {svv.x, svv.y, svv.z, svv.w};

    // no-slip (sdf <= 0)
    {
        float m = 0.0f;
        #pragma unroll
        for (int l = 0; l < 4; l++) {
            float q = Fv[0][l]*Fv[0][l] + Fv[1][l]*Fv[1][l] + Fv[2][l]*Fv[2][l];
            m += (Sv[l] <= 0.0f) ? q : 0.0f;
        }
        acc += c_sc_noslip * m;
    }

    // inlet / outlet
    if (wq == 0) {
        float du0 = Fv[0][0] - 1.0f;
        acc += c_sc_inlet * (du0*du0 + Fv[1][0]*Fv[1][0] + Fv[2][0]*Fv[2][0]);
    }
    if (wq == 15) {
        float a0 = Fv[0][3] - Fv[0][2];
        float a1 = Fv[1][3] - Fv[1][2];
        float a2 = Fv[2][3] - Fv[2][2];
        acc += c_sc_outlet * (a0*a0 + a1*a1 + a2*a2);
    }

    const bool yz_interior = (d >= 1) & (d <= ND - 2) & (h >= 1) & (h <= NH - 2);

    // ---- x-edge neighbors via warp shuffle (uniform, full warp) ----
    // Row-crossing lanes (wq==0/15) are zero-masked by wgt[] below.
    float Lcs[3], Rcs[3];
    #pragma unroll
    for (int c = 0; c < 3; c++) {
        Lcs[c] = __shfl_up_sync  (FULLMASK, Fv[c][3], 1);
        Rcs[c] = __shfl_down_sync(FULLMASK, Fv[c][0], 1);
    }

    // --- pressure block: gradients; p regs die at end of block ---
    float gpx[4], gpy[4], gpz[4];
    {
        float4 pc = cv[3];
        float pL = __shfl_up_sync  (FULLMASK, pc.w, 1);
        float pR = __shfl_down_sync(FULLMASK, pc.x, 1);
        if (yz_interior) {
            const float* cb = fb + 3 * CS;
            float4 yp = ld4(cb + OY), ym = ld4(cb - OY);
            float4 zp = ld4(cb + OZ), zm = ld4(cb - OZ);
            gpy[0] = (yp.x - ym.x) * c_inv2dy;
            gpy[1] = (yp.y - ym.y) * c_inv2dy;
            gpy[2] = (yp.z - ym.z) * c_inv2dy;
            gpy[3] = (yp.w - ym.w) * c_inv2dy;
            gpz[0] = (zp.x - zm.x) * c_inv2dz;
            gpz[1] = (zp.y - zm.y) * c_inv2dz;
            gpz[2] = (zp.z - zm.z) * c_inv2dz;
            gpz[3] = (zp.w - zm.w) * c_inv2dz;
            gpx[0] = (pc.y - pL)   * c_inv2dx;
            gpx[1] = (pc.z - pc.x) * c_inv2dx;
            gpx[2] = (pc.w - pc.y) * c_inv2dx;
            gpx[3] = (pR   - pc.z) * c_inv2dx;
        }
    }

    // --- interior continuity + momentum, velocity channels streamed ---
    if (yz_interior) {
        float wgt[4];
        wgt[0] = (wq != 0  && Sv[0] > 0.0f) ? 1.0f : 0.0f;
        wgt[1] = (Sv[1] > 0.0f) ? 1.0f : 0.0f;
        wgt[2] = (Sv[2] > 0.0f) ? 1.0f : 0.0f;
        wgt[3] = (wq != 15 && Sv[3] > 0.0f) ? 1.0f : 0.0f;

        float div[4] = {0.0f, 0.0f, 0.0f, 0.0f};
        float msum = 0.0f;

        #pragma unroll
        for (int c = 0; c < 3; c++) {
            const float* cb = fb + c * CS;
            float4 yp = ld4(cb + OY), ym = ld4(cb - OY);
            float4 zp = ld4(cb + OZ), zm = ld4(cb - OZ);

            float gy[4], sy[4], gz[4], sz[4];
            gy[0] = (yp.x - ym.x) * c_inv2dy; sy[0] = yp.x + ym.x;
            gy[1] = (yp.y - ym.y) * c_inv2dy; sy[1] = yp.y + ym.y;
            gy[2] = (yp.z - ym.z) * c_inv2dy; sy[2] = yp.z + ym.z;
            gy[3] = (yp.w - ym.w) * c_inv2dy; sy[3] = yp.w + ym.w;
            gz[0] = (zp.x - zm.x) * c_inv2dz; sz[0] = zp.x + zm.x;
            gz[1] = (zp.y - zm.y) * c_inv2dz; sz[1] = zp.y + zm.y;
            gz[2] = (zp.z - zm.z) * c_inv2dz; sz[2] = zp.z + zm.z;
            gz[3] = (zp.w - zm.w) * c_inv2dz; sz[3] = zp.w + zm.w;

            #pragma unroll
            for (int l = 0; l < 4; l++) {
                float ce = Fv[c][l];
                float xm = (l == 0) ? Lcs[c] : Fv[c][l - 1];
                float xp = (l == 3) ? Rcs[c] : Fv[c][l + 1];
                float gx = (xp - xm) * c_inv2dx;
                float lap = (xp + xm - 2.0f * ce) * c_idx2
                          + (sy[l]   - 2.0f * ce) * c_idy2
                          + (sz[l]   - 2.0f * ce) * c_idz2;
                float gp  = (c == 0) ? gpx[l] : (c == 1) ? gpy[l] : gpz[l];
                float res = Fv[0][l] * gx + Fv[1][l] * gy[l] + Fv[2][l] * gz[l]
                          + gp - INV_RE * lap;
                msum   += wgt[l] * res * res;
                div[l] += (c == 0) ? gx : (c == 1) ? gy[l] : gz[l];
            }
        }

        #pragma unroll
        for (int l = 0; l < 4; l++)
            msum += wgt[l] * div[l] * div[l];

        acc += c_sc_cm * msum;
    }

    // ---- deferred field MSE: gt has been streaming in the background ----
    asm volatile("cp.async.wait_group 0;\n" ::: "memory");
    {
        float m = 0.0f;
        #pragma unroll
        for (int c = 0; c < 4; c++) {
            float4 g = gbuf[tid][c];
            float d0 = cv[c].x - g.x, d1 = cv[c].y - g.y;
            float d2 = cv[c].z - g.z, d3 = cv[c].w - g.w;
            m += d0*d0 + d1*d1 + d2*d2 + d3*d3;
        }
        acc += c_sc_field * m;
    }

    // ---- reduction: warp shfl (f32) -> block (f64) -> global atomic ----
    #pragma unroll
    for (int o = 16; o > 0; o >>= 1)
        acc += __shfl_down_sync(FULLMASK, acc, o);

    if ((tid & 31) == 0)
        warpsum[tid >> 5] = (double)acc;
    __syncthreads();

    if (tid == 0) {
        double t = 0.0;
        #pragma unroll
        for (int i = 0; i < 8; i++) t += warpsum[i];
        atomicAdd(&g_acc, t);
        __threadfence();
        unsigned int ticket = atomicAdd(&g_count, 1u);
        if (ticket == (unsigned)(gridDim.x - 1)) {
            double tot = atomicAdd(&g_acc, 0.0);
            out[0] = (float)tot;
            g_acc = 0.0;       // reset for next graph replay
            g_count = 0u;
            __threadfence();
        }
    }
}

extern "C" void kernel_launch(void* const* d_in, const int* in_sizes, int n_in,
                              void* d_out, int out_size)
{
    const float* field    = (const float*)d_in[0];
    const float* ct       = (const float*)d_in[1];
    const float* gt_field = (const float*)d_in[2];
    const float* gt_ct    = (const float*)d_in[3];
    const float* sdf      = (const float*)d_in[4];

    k_loss<<<NBLK, 256>>>(field, ct, gt_field, gt_ct, sdf, (float*)d_out);
}

// round 13
// speedup vs baseline: 2.0967x; 1.7417x over previous
#include <cuda_runtime.h>

// Shapes: field/gt_field (8,4,64,128,64) f32, ct/gt_ct (8,1) f32, sdf (8,1,64,128,64) f32.
// Output: scalar f32 total loss.
// Persistent grid (608 blocks = 4/SM), grid-stride loop over 7 iterations with the
// proven R9 body: float4 along W, 9-LDG batched DRAM front, shfl x-edges,
// channel-streamed interior. Pure LDG/L1 path (cp.async harmful: R7/R11/R12).

#define NB 8
#define ND 64
#define NH 128
#define NW 64
#define SP (ND*NH*NW)
#define CS SP
#define NPTS (NB*SP)
#define NVEC (NPTS/4)            // 1048576 float4 quads
#define NBLKP 608                 // 152 SMs * 4 CTAs
#define STRIDE (NBLKP*256)        // 155648
#define NITER 7                   // ceil(NVEC/STRIDE)

#define DXd ((2.0 + 0.5) / 63.0)
#define DYd ((0.5 + 0.5) / 127.0)
#define DZd ((0.3 + 0.5) / 63.0)

constexpr float c_inv2dx = (float)(1.0 / (2.0 * DXd));
constexpr float c_inv2dy = (float)(1.0 / (2.0 * DYd));
constexpr float c_inv2dz = (float)(1.0 / (2.0 * DZd));
constexpr float c_idx2   = (float)(1.0 / (DXd * DXd));
constexpr float c_idy2   = (float)(1.0 / (DYd * DYd));
constexpr float c_idz2   = (float)(1.0 / (DZd * DZd));

constexpr float c_sc_field  = (float)(1.0  / (double)(NB*4*SP));
constexpr float c_sc_ct     = (float)(10.0 / 8.0);
constexpr float c_sc_cm     = (float)(1.0  / (double)(NB*(ND-2)*(NH-2)*(NW-2)));
constexpr float c_sc_noslip = (float)(10.0 / (double)NPTS);
constexpr float c_sc_inlet  = (float)(5.0  / (double)(NB*ND*NH));
constexpr float c_sc_outlet = (float)(1.0  / (double)(NB*ND*NH));

#define INV_RE 1.0e-6f
#define OY NW
#define OZ (NH*NW)
#define FULLMASK 0xffffffffu

__device__ double g_acc = 0.0;
__device__ unsigned int g_count = 0;

__device__ __forceinline__ float4 ld4(const float* p) {
    return *reinterpret_cast<const float4*>(p);
}
__device__ __forceinline__ float4 ld4cs(const float* p) {
    return __ldcs(reinterpret_cast<const float4*>(p));
}

__global__ void __launch_bounds__(256, 4) k_loss(
    const float* __restrict__ field,
    const float* __restrict__ ct,
    const float* __restrict__ gt_field,
    const float* __restrict__ gt_ct,
    const float* __restrict__ sdf,
    float* __restrict__ out)
{
    __shared__ double warpsum[8];

    const int tid  = threadIdx.x;
    const int vid0 = blockIdx.x * 256 + tid;

    float acc = 0.0f;

    #pragma unroll 1
    for (int it = 0; it < NITER; it++) {
        const int vid = vid0 + it * STRIDE;
        if (vid >= NVEC) break;     // whole-warp exit (STRIDE, NVEC mult of 32)

        const int wq = vid & 15;
        const int h  = (vid >> 4)  & (NH - 1);
        const int d  = (vid >> 11) & (ND - 1);
        const int b  = vid >> 17;

        const int sidx  = ((d * NH + h) << 6) + (wq << 2);
        const float* fb = field    + b * (4 * SP) + sidx;
        const float* gb = gt_field + b * (4 * SP) + sidx;

        if (vid < 8) {
            float dct = ct[vid] - gt_ct[vid];
            acc += c_sc_ct * dct * dct;
        }

        // ---- batched DRAM front: 9 LDG.128 back-to-back ----
        float4 cv[4], gv[4], svv;
        #pragma unroll
        for (int c = 0; c < 4; c++) cv[c] = ld4(fb + c * CS);
        #pragma unroll
        for (int c = 0; c < 4; c++) gv[c] = ld4cs(gb + c * CS);
        svv = ld4cs(sdf + b * SP + sidx);

        // velocity centers as scalars
        float Fv[3][4];
        #pragma unroll
        for (int c = 0; c < 3; c++) {
            Fv[c][0] = cv[c].x; Fv[c][1] = cv[c].y;
            Fv[c][2] = cv[c].z; Fv[c][3] = cv[c].w;
        }

        // field MSE, all 4 channels
        {
            float m = 0.0f;
            #pragma unroll
            for (int c = 0; c < 4; c++) {
                float d0 = cv[c].x - gv[c].x, d1 = cv[c].y - gv[c].y;
                float d2 = cv[c].z - gv[c].z, d3 = cv[c].w - gv[c].w;
                m += d0*d0 + d1*d1 + d2*d2 + d3*d3;
            }
            acc += c_sc_field * m;
        }

        float Sv[4] = {svv.x, svv.y, svv.z, svv.w};

        // no-slip (sdf <= 0)
        {
            float m = 0.0f;
            #pragma unroll
            for (int l = 0; l < 4; l++) {
                float q = Fv[0][l]*Fv[0][l] + Fv[1][l]*Fv[1][l] + Fv[2][l]*Fv[2][l];
                m += (Sv[l] <= 0.0f) ? q : 0.0f;
            }
            acc += c_sc_noslip * m;
        }

        // inlet / outlet
        if (wq == 0) {
            float du0 = Fv[0][0] - 1.0f;
            acc += c_sc_inlet * (du0*du0 + Fv[1][0]*Fv[1][0] + Fv[2][0]*Fv[2][0]);
        }
        if (wq == 15) {
            float a0 = Fv[0][3] - Fv[0][2];
            float a1 = Fv[1][3] - Fv[1][2];
            float a2 = Fv[2][3] - Fv[2][2];
            acc += c_sc_outlet * (a0*a0 + a1*a1 + a2*a2);
        }

        const bool yz_interior = (d >= 1) & (d <= ND - 2) & (h >= 1) & (h <= NH - 2);

        // x-edge neighbors via warp shuffle (full warp active here)
        float Lcs[3], Rcs[3];
        #pragma unroll
        for (int c = 0; c < 3; c++) {
            Lcs[c] = __shfl_up_sync  (FULLMASK, Fv[c][3], 1);
            Rcs[c] = __shfl_down_sync(FULLMASK, Fv[c][0], 1);
        }

        // pressure block: gradients; p regs die at end
        float gpx[4], gpy[4], gpz[4];
        {
            float4 pc = cv[3];
            float pL = __shfl_up_sync  (FULLMASK, pc.w, 1);
            float pR = __shfl_down_sync(FULLMASK, pc.x, 1);
            if (yz_interior) {
                const float* cb = fb + 3 * CS;
                float4 yp = ld4(cb + OY), ym = ld4(cb - OY);
                float4 zp = ld4(cb + OZ), zm = ld4(cb - OZ);
                gpy[0] = (yp.x - ym.x) * c_inv2dy;
                gpy[1] = (yp.y - ym.y) * c_inv2dy;
                gpy[2] = (yp.z - ym.z) * c_inv2dy;
                gpy[3] = (yp.w - ym.w) * c_inv2dy;
                gpz[0] = (zp.x - zm.x) * c_inv2dz;
                gpz[1] = (zp.y - zm.y) * c_inv2dz;
                gpz[2] = (zp.z - zm.z) * c_inv2dz;
                gpz[3] = (zp.w - zm.w) * c_inv2dz;
                gpx[0] = (pc.y - pL)   * c_inv2dx;
                gpx[1] = (pc.z - pc.x) * c_inv2dx;
                gpx[2] = (pc.w - pc.y) * c_inv2dx;
                gpx[3] = (pR   - pc.z) * c_inv2dx;
            }
        }

        // interior continuity + momentum, velocity channels streamed
        if (yz_interior) {
            float wgt[4];
            wgt[0] = (wq != 0  && Sv[0] > 0.0f) ? 1.0f : 0.0f;
            wgt[1] = (Sv[1] > 0.0f) ? 1.0f : 0.0f;
            wgt[2] = (Sv[2] > 0.0f) ? 1.0f : 0.0f;
            wgt[3] = (wq != 15 && Sv[3] > 0.0f) ? 1.0f : 0.0f;

            float div[4] = {0.0f, 0.0f, 0.0f, 0.0f};
            float msum = 0.0f;

            #pragma unroll
            for (int c = 0; c < 3; c++) {
                const float* cb = fb + c * CS;
                float4 yp = ld4(cb + OY), ym = ld4(cb - OY);
                float4 zp = ld4(cb + OZ), zm = ld4(cb - OZ);

                float gy[4], sy[4], gz[4], sz[4];
                gy[0] = (yp.x - ym.x) * c_inv2dy; sy[0] = yp.x + ym.x;
                gy[1] = (yp.y - ym.y) * c_inv2dy; sy[1] = yp.y + ym.y;
                gy[2] = (yp.z - ym.z) * c_inv2dy; sy[2] = yp.z + ym.z;
                gy[3] = (yp.w - ym.w) * c_inv2dy; sy[3] = yp.w + ym.w;
                gz[0] = (zp.x - zm.x) * c_inv2dz; sz[0] = zp.x + zm.x;
                gz[1] = (zp.y - zm.y) * c_inv2dz; sz[1] = zp.y + zm.y;
                gz[2] = (zp.z - zm.z) * c_inv2dz; sz[2] = zp.z + zm.z;
                gz[3] = (zp.w - zm.w) * c_inv2dz; sz[3] = zp.w + zm.w;

                #pragma unroll
                for (int l = 0; l < 4; l++) {
                    float ce = Fv[c][l];
                    float xm = (l == 0) ? Lcs[c] : Fv[c][l - 1];
                    float xp = (l == 3) ? Rcs[c] : Fv[c][l + 1];
                    float gx = (xp - xm) * c_inv2dx;
                    float lap = (xp + xm - 2.0f * ce) * c_idx2
                              + (sy[l]   - 2.0f * ce) * c_idy2
                              + (sz[l]   - 2.0f * ce) * c_idz2;
                    float gp  = (c == 0) ? gpx[l] : (c == 1) ? gpy[l] : gpz[l];
                    float res = Fv[0][l] * gx + Fv[1][l] * gy[l] + Fv[2][l] * gz[l]
                              + gp - INV_RE * lap;
                    msum   += wgt[l] * res * res;
                    div[l] += (c == 0) ? gx : (c == 1) ? gy[l] : gz[l];
                }
            }

            #pragma unroll
            for (int l = 0; l < 4; l++)
                msum += wgt[l] * div[l] * div[l];

            acc += c_sc_cm * msum;
        }
    }

    // ---- reduction (once per CTA): warp shfl (f32) -> block (f64) -> atomic ----
    #pragma unroll
    for (int o = 16; o > 0; o >>= 1)
        acc += __shfl_down_sync(FULLMASK, acc, o);

    if ((tid & 31) == 0)
        warpsum[tid >> 5] = (double)acc;
    __syncthreads();

    if (tid == 0) {
        double t = 0.0;
        #pragma unroll
        for (int i = 0; i < 8; i++) t += warpsum[i];
        atomicAdd(&g_acc, t);
        __threadfence();
        unsigned int ticket = atomicAdd(&g_count, 1u);
        if (ticket == (unsigned)(gridDim.x - 1)) {
            double tot = atomicAdd(&g_acc, 0.0);
            out[0] = (float)tot;
            g_acc = 0.0;       // reset for next graph replay
            g_count = 0u;
            __threadfence();
        }
    }
}

extern "C" void kernel_launch(void* const* d_in, const int* in_sizes, int n_in,
                              void* d_out, int out_size)
{
    const float* field    = (const float*)d_in[0];
    const float* ct       = (const float*)d_in[1];
    const float* gt_field = (const float*)d_in[2];
    const float* gt_ct    = (const float*)d_in[3];
    const float* sdf      = (const float*)d_in[4];

    k_loss<<<NBLKP, 256>>>(field, ct, gt_field, gt_ct, sdf, (float*)d_out);
}